// round 5
// baseline (speedup 1.0000x reference)
#include <cuda_runtime.h>
#include <cuda_bf16.h>
#include <math.h>
#include <stdint.h>

// ---------------------------------------------------------------------------
// Problem constants
// ---------------------------------------------------------------------------
#define BATCH   8192
#define IN_DIM  4096
#define OUT_DIM 2048
#define DEPTH   9
#define RSTEPS  27
#define WIN     55
#define CENTER  27

// GEMM tiling
#define BM 128
#define BN 128
#define BK 32
#define NKT (IN_DIM / BK)            // 128
#define STAGES 3
#define MAT_BYTES 8192               // one 128x32 bf16 tile
#define STAGE_BYTES (4 * MAT_BYTES)  // Ahi, Alo, Bhi, Blo
#define SMEM_TOTAL (STAGES * STAGE_BYTES)  // 98304

#define AHI 0
#define ALO 8192
#define BHI 16384
#define BLO 24576

// ---------------------------------------------------------------------------
// Device-global scratch (static: no runtime allocation)
// ---------------------------------------------------------------------------
__device__ float         g_pb[OUT_DIM];
__device__ __nv_bfloat16 g_xhi[(size_t)BATCH * IN_DIM];
__device__ __nv_bfloat16 g_xlo[(size_t)BATCH * IN_DIM];
__device__ __nv_bfloat16 g_wThi[(size_t)OUT_DIM * IN_DIM];   // W^T [N][K]
__device__ __nv_bfloat16 g_wTlo[(size_t)OUT_DIM * IN_DIM];

// ---------------------------------------------------------------------------
// PTX helpers (base sm_103 ISA only: cp.async / ldmatrix / mma.sync)
// ---------------------------------------------------------------------------
__device__ __forceinline__ uint32_t smem_u32(const void* p) {
    uint32_t a;
    asm("{ .reg .u64 t; cvta.to.shared.u64 t, %1; cvt.u32.u64 %0, t; }"
        : "=r"(a) : "l"(p));
    return a;
}
__device__ __forceinline__ void cpasync16(uint32_t dst, const void* src) {
    asm volatile("cp.async.cg.shared.global [%0], [%1], 16;"
                 :: "r"(dst), "l"(src));
}
#define CP_COMMIT() asm volatile("cp.async.commit_group;" ::: "memory")
#define CP_WAIT1()  asm volatile("cp.async.wait_group 1;"  ::: "memory")

#define LDSM_X4(d, a) \
    asm volatile("ldmatrix.sync.aligned.m8n8.x4.shared.b16 {%0,%1,%2,%3}, [%4];" \
        : "=r"((d)[0]), "=r"((d)[1]), "=r"((d)[2]), "=r"((d)[3]) : "r"(a))
#define LDSM_X2(d, a) \
    asm volatile("ldmatrix.sync.aligned.m8n8.x2.shared.b16 {%0,%1}, [%2];" \
        : "=r"((d)[0]), "=r"((d)[1]) : "r"(a))

#define MMA16816(c, a, b) \
    asm volatile("mma.sync.aligned.m16n8k16.row.col.f32.bf16.bf16.f32 " \
        "{%0,%1,%2,%3}, {%4,%5,%6,%7}, {%8,%9}, {%0,%1,%2,%3};" \
        : "+f"((c)[0]), "+f"((c)[1]), "+f"((c)[2]), "+f"((c)[3]) \
        : "r"((a)[0]), "r"((a)[1]), "r"((a)[2]), "r"((a)[3]), \
          "r"((b)[0]), "r"((b)[1]))

// Swizzled smem offset for logical (row 0..127, 16B-chunk cc 0..3).
// Physical: 64 rows x 128B; chunk8 = ((row&1)<<2)|cc, XOR (p&7).
// 8 consecutive logical rows at fixed cc hit 8 distinct 16B banks.
__device__ __forceinline__ uint32_t swz(uint32_t base, int row, int cc) {
    int p  = row >> 1;
    int c8 = ((row & 1) << 2) | cc;
    return base + p * 128 + ((c8 ^ (p & 7)) << 4);
}

// ---------------------------------------------------------------------------
// Kernel 1: universal probs (dependency-cone trick) + bias -> g_pb
// ---------------------------------------------------------------------------
__global__ void probs_kernel(const float* __restrict__ uw,
                             const float* __restrict__ bias) {
    int o = blockIdx.x * blockDim.x + threadIdx.x;
    if (o >= OUT_DIM) return;
    float w[WIN];
#pragma unroll
    for (int j = 0; j < WIN; j++) w[j] = 0.015625f;   // 1/sqrt(4096)
#pragma unroll
    for (int t = 0; t < RSTEPS; t++) {
        const int d = t / 3, g = t % 3;
        float ang = uw[(size_t)d * IN_DIM * OUT_DIM + (size_t)o * OUT_DIM + g];
        float s, c;
        sincosf(ang, &s, &c);
        float nw[WIN];
        nw[0] = w[0]; nw[WIN - 1] = w[WIN - 1];
#pragma unroll
        for (int j = 1; j < WIN - 1; j++)
            nw[j] = c * w[j] - s * w[j + 1] + s * w[j - 1];
#pragma unroll
        for (int j = 0; j < WIN; j++) w[j] = nw[j];
    }
    g_pb[o] = w[CENTER] * w[CENTER] + bias[o];
}

// ---------------------------------------------------------------------------
// Kernel 2: split x -> (hi, lo) bf16
// ---------------------------------------------------------------------------
__global__ void split_x_kernel(const float* __restrict__ x) {
    size_t i = ((size_t)blockIdx.x * blockDim.x + threadIdx.x) * 4;
    float4 v = *(const float4*)(x + i);
    __nv_bfloat16 h0 = __float2bfloat16(v.x);
    __nv_bfloat16 h1 = __float2bfloat16(v.y);
    __nv_bfloat16 h2 = __float2bfloat16(v.z);
    __nv_bfloat16 h3 = __float2bfloat16(v.w);
    __nv_bfloat162* ph = (__nv_bfloat162*)(g_xhi + i);
    __nv_bfloat162* pl = (__nv_bfloat162*)(g_xlo + i);
    ph[0] = __nv_bfloat162(h0, h1);
    ph[1] = __nv_bfloat162(h2, h3);
    pl[0] = __nv_bfloat162(__float2bfloat16(v.x - __bfloat162float(h0)),
                           __float2bfloat16(v.y - __bfloat162float(h1)));
    pl[1] = __nv_bfloat162(__float2bfloat16(v.z - __bfloat162float(h2)),
                           __float2bfloat16(v.w - __bfloat162float(h3)));
}

// ---------------------------------------------------------------------------
// Kernel 3: transpose + split W[k][n] -> wT_hi/lo[n][k]
// ---------------------------------------------------------------------------
__global__ void split_w_kernel(const float* __restrict__ W) {
    __shared__ float t[32][33];
    const int n0 = blockIdx.x * 32, k0 = blockIdx.y * 32;
    const int tx = threadIdx.x, ty = threadIdx.y;   // 32 x 8
#pragma unroll
    for (int i = 0; i < 32; i += 8)
        t[ty + i][tx] = W[(size_t)(k0 + ty + i) * OUT_DIM + n0 + tx];
    __syncthreads();
#pragma unroll
    for (int i = 0; i < 32; i += 8) {
        float v = t[tx][ty + i];
        __nv_bfloat16 h = __float2bfloat16(v);
        size_t o = (size_t)(n0 + ty + i) * IN_DIM + k0 + tx;
        g_wThi[o] = h;
        g_wTlo[o] = __float2bfloat16(v - __bfloat162float(h));
    }
}

// ---------------------------------------------------------------------------
// Kernel 4: C = tanh(x @ W + g_pb) via bf16x3 mma.sync GEMM.
// 128x128x32 CTA tile, 16 warps (4x4), warp tile 32x32, 3-stage cp.async.
// ---------------------------------------------------------------------------
__global__ __launch_bounds__(512, 1)
void gemm_bf16x3_kernel(float* __restrict__ out) {
    extern __shared__ char smem[];
    const uint32_t sb = smem_u32(smem);

    const int tid  = threadIdx.x;
    const int lane = tid & 31;
    const int wid  = tid >> 5;
    const int wm   = wid >> 2;          // 0..3  -> m offset wm*32
    const int wn   = wid & 3;           // 0..3  -> n offset wn*32
    const int gid  = lane >> 2;
    const int tg   = lane & 3;
    const int bm   = blockIdx.y * BM;
    const int bn   = blockIdx.x * BN;

    // --- global load mapping: 2048 x 16B chunks/stage, 4 per thread ---
    const int rr = tid >> 2;            // rows 0..127
    const int cc = tid & 3;             // 16B chunk within 64B row

    const __nv_bfloat16* pAh = g_xhi  + (size_t)(bm + rr) * IN_DIM + cc * 8;
    const __nv_bfloat16* pAl = g_xlo  + (size_t)(bm + rr) * IN_DIM + cc * 8;
    const __nv_bfloat16* pBh = g_wThi + (size_t)(bn + rr) * IN_DIM + cc * 8;
    const __nv_bfloat16* pBl = g_wTlo + (size_t)(bn + rr) * IN_DIM + cc * 8;

    const uint32_t dAh = swz(AHI, rr, cc);
    const uint32_t dAl = swz(ALO, rr, cc);
    const uint32_t dBh = swz(BHI, rr, cc);
    const uint32_t dBl = swz(BLO, rr, cc);

    int kload = 0;
#define ISSUE_STAGE(stg)                                                     \
    do {                                                                     \
        uint32_t s_ = sb + (stg) * STAGE_BYTES;                              \
        cpasync16(s_ + dAh, pAh + kload);                                    \
        cpasync16(s_ + dAl, pAl + kload);                                    \
        cpasync16(s_ + dBh, pBh + kload);                                    \
        cpasync16(s_ + dBl, pBl + kload);                                    \
        kload += BK;                                                         \
    } while (0)

    // Prologue: stages 0 and 1
    ISSUE_STAGE(0); CP_COMMIT();
    ISSUE_STAGE(1); CP_COMMIT();

    float acc[2][4][4];
#pragma unroll
    for (int i = 0; i < 2; i++)
#pragma unroll
        for (int j = 0; j < 4; j++)
#pragma unroll
            for (int q = 0; q < 4; q++) acc[i][j][q] = 0.0f;

    // Per-lane ldmatrix logical coordinates
    const int a_rl = lane & 15;           // A: rows m0..m0+15
    const int a_ch = lane >> 4;           // A: +0 / +1 chunk
    const int b_rl = lane & 7;            // B: rows n0..n0+7
    const int b_ch = (lane >> 3) & 1;     // B: +0 / +1 chunk

    // Precompute swizzled offsets (relative to stage base) for both ks halves
    uint32_t oA[2][2], oB[2][4];          // [ks][mi] / [ks][ni]
#pragma unroll
    for (int ks = 0; ks < 2; ks++) {
        const int ccA = ks * 2 + a_ch;
        const int ccB = ks * 2 + b_ch;
#pragma unroll
        for (int mi = 0; mi < 2; mi++)
            oA[ks][mi] = swz(0, wm * 32 + mi * 16 + a_rl, ccA);
#pragma unroll
        for (int ni = 0; ni < 4; ni++)
            oB[ks][ni] = swz(0, wn * 32 + ni * 8 + b_rl, ccB);
    }

    int stage = 0;
#pragma unroll 1
    for (int kt = 0; kt < NKT; kt++) {
        CP_WAIT1();
        __syncthreads();

        if (kt + 2 < NKT) {
            int nst = stage + 2; if (nst >= STAGES) nst -= STAGES;
            ISSUE_STAGE(nst);
        }
        CP_COMMIT();

        const uint32_t s_ = sb + stage * STAGE_BYTES;

#pragma unroll
        for (int ks = 0; ks < 2; ks++) {
            uint32_t ah[2][4], al[2][4], bh[4][2], bl[4][2];
#pragma unroll
            for (int mi = 0; mi < 2; mi++) {
                LDSM_X4(ah[mi], s_ + AHI + oA[ks][mi]);
                LDSM_X4(al[mi], s_ + ALO + oA[ks][mi]);
            }
#pragma unroll
            for (int ni = 0; ni < 4; ni++) {
                LDSM_X2(bh[ni], s_ + BHI + oB[ks][ni]);
                LDSM_X2(bl[ni], s_ + BLO + oB[ks][ni]);
            }
            // Product-major order: no back-to-back MMAs share an accumulator
#pragma unroll
            for (int mi = 0; mi < 2; mi++)
#pragma unroll
                for (int ni = 0; ni < 4; ni++)
                    MMA16816(acc[mi][ni], ah[mi], bh[ni]);
#pragma unroll
            for (int mi = 0; mi < 2; mi++)
#pragma unroll
                for (int ni = 0; ni < 4; ni++)
                    MMA16816(acc[mi][ni], ah[mi], bl[ni]);
#pragma unroll
            for (int mi = 0; mi < 2; mi++)
#pragma unroll
                for (int ni = 0; ni < 4; ni++)
                    MMA16816(acc[mi][ni], al[mi], bh[ni]);
        }
        stage++; if (stage >= STAGES) stage = 0;
    }

    // ------------------- epilogue: +pb, tanh, store -------------------
    float pbv[4][2];
#pragma unroll
    for (int ni = 0; ni < 4; ni++) {
        const int col = bn + wn * 32 + ni * 8 + tg * 2;
        pbv[ni][0] = g_pb[col];
        pbv[ni][1] = g_pb[col + 1];
    }
#pragma unroll
    for (int mi = 0; mi < 2; mi++) {
        const int r0 = bm + wm * 32 + mi * 16 + gid;
#pragma unroll
        for (int ni = 0; ni < 4; ni++) {
            const int col = bn + wn * 32 + ni * 8 + tg * 2;
            float2 v0, v1;
            v0.x = tanhf(acc[mi][ni][0] + pbv[ni][0]);
            v0.y = tanhf(acc[mi][ni][1] + pbv[ni][1]);
            v1.x = tanhf(acc[mi][ni][2] + pbv[ni][0]);
            v1.y = tanhf(acc[mi][ni][3] + pbv[ni][1]);
            *(float2*)(out + (size_t)r0 * OUT_DIM + col)       = v0;
            *(float2*)(out + (size_t)(r0 + 8) * OUT_DIM + col) = v1;
        }
    }
}

// ---------------------------------------------------------------------------
// Host launch
// ---------------------------------------------------------------------------
extern "C" void kernel_launch(void* const* d_in, const int* in_sizes, int n_in,
                              void* d_out, int out_size) {
    const float *x = nullptr, *uw = nullptr, *cw = nullptr, *cb = nullptr;
    for (int i = 0; i < n_in; i++) {
        switch (in_sizes[i]) {
            case BATCH * IN_DIM:           x  = (const float*)d_in[i]; break;
            case DEPTH * IN_DIM * OUT_DIM: uw = (const float*)d_in[i]; break;
            case IN_DIM * OUT_DIM:         cw = (const float*)d_in[i]; break;
            case OUT_DIM:                  cb = (const float*)d_in[i]; break;
            default: break;
        }
    }
    float* out = (float*)d_out;

    probs_kernel<<<OUT_DIM / 256, 256>>>(uw, cb);
    split_x_kernel<<<(BATCH * IN_DIM) / (4 * 256), 256>>>(x);
    split_w_kernel<<<dim3(OUT_DIM / 32, IN_DIM / 32), dim3(32, 8)>>>(cw);

    static int attr_done = 0;
    if (!attr_done) {
        cudaFuncSetAttribute(gemm_bf16x3_kernel,
                             cudaFuncAttributeMaxDynamicSharedMemorySize,
                             SMEM_TOTAL);
        attr_done = 1;
    }
    dim3 grid(OUT_DIM / BN, BATCH / BM);   // (16, 64)
    gemm_bf16x3_kernel<<<grid, 512, SMEM_TOTAL>>>(out);
}

// round 6
// speedup vs baseline: 1.0332x; 1.0332x over previous
#include <cuda_runtime.h>
#include <cuda_bf16.h>
#include <math.h>
#include <stdint.h>

// ---------------------------------------------------------------------------
// Problem constants
// ---------------------------------------------------------------------------
#define BATCH   8192
#define IN_DIM  4096
#define OUT_DIM 2048
#define DEPTH   9
#define RSTEPS  27
#define WIN     55
#define CENTER  27

// GEMM tiling: 128x64 CTA tile, 2 CTAs/SM
#define BM 128
#define BN 64
#define BK 32
#define NKT (IN_DIM / BK)            // 128
#define STAGES 4
// Stage layout: Ahi 8K | Alo 8K | Bhi 4K | Blo 4K
#define AHI 0
#define ALO 8192
#define BHI 16384
#define BLO 20480
#define STAGE_BYTES 24576
#define SMEM_TOTAL (STAGES * STAGE_BYTES)   // 98304/CTA -> 2 CTAs = 192KB/SM

// ---------------------------------------------------------------------------
// Device-global scratch (static: no runtime allocation)
// ---------------------------------------------------------------------------
__device__ float         g_pb[OUT_DIM];
__device__ __nv_bfloat16 g_xhi[(size_t)BATCH * IN_DIM];
__device__ __nv_bfloat16 g_xlo[(size_t)BATCH * IN_DIM];
__device__ __nv_bfloat16 g_wThi[(size_t)OUT_DIM * IN_DIM];   // W^T [N][K]
__device__ __nv_bfloat16 g_wTlo[(size_t)OUT_DIM * IN_DIM];

// ---------------------------------------------------------------------------
// PTX helpers (base sm_103 ISA only: cp.async / ldmatrix / mma.sync)
// ---------------------------------------------------------------------------
__device__ __forceinline__ uint32_t smem_u32(const void* p) {
    uint32_t a;
    asm("{ .reg .u64 t; cvta.to.shared.u64 t, %1; cvt.u32.u64 %0, t; }"
        : "=r"(a) : "l"(p));
    return a;
}
__device__ __forceinline__ void cpasync16(uint32_t dst, const void* src) {
    asm volatile("cp.async.cg.shared.global [%0], [%1], 16;"
                 :: "r"(dst), "l"(src));
}
#define CP_COMMIT() asm volatile("cp.async.commit_group;" ::: "memory")
#define CP_WAIT2()  asm volatile("cp.async.wait_group 2;"  ::: "memory")

#define LDSM_X4(d, a) \
    asm volatile("ldmatrix.sync.aligned.m8n8.x4.shared.b16 {%0,%1,%2,%3}, [%4];" \
        : "=r"((d)[0]), "=r"((d)[1]), "=r"((d)[2]), "=r"((d)[3]) : "r"(a))
#define LDSM_X2(d, a) \
    asm volatile("ldmatrix.sync.aligned.m8n8.x2.shared.b16 {%0,%1}, [%2];" \
        : "=r"((d)[0]), "=r"((d)[1]) : "r"(a))

#define MMA16816(c, a, b) \
    asm volatile("mma.sync.aligned.m16n8k16.row.col.f32.bf16.bf16.f32 " \
        "{%0,%1,%2,%3}, {%4,%5,%6,%7}, {%8,%9}, {%0,%1,%2,%3};" \
        : "+f"((c)[0]), "+f"((c)[1]), "+f"((c)[2]), "+f"((c)[3]) \
        : "r"((a)[0]), "r"((a)[1]), "r"((a)[2]), "r"((a)[3]), \
          "r"((b)[0]), "r"((b)[1]))

// Swizzled smem offset for logical (row, 16B-chunk cc 0..3) of a 64B-row tile.
// Physical: 128B rows packing 2 logical rows; chunk8 = ((row&1)<<2)|cc XOR (p&7).
__device__ __forceinline__ uint32_t swz(uint32_t base, int row, int cc) {
    int p  = row >> 1;
    int c8 = ((row & 1) << 2) | cc;
    return base + p * 128 + ((c8 ^ (p & 7)) << 4);
}

// ---------------------------------------------------------------------------
// Kernel 1: universal probs (dependency-cone trick) + bias -> g_pb
// ---------------------------------------------------------------------------
__global__ void probs_kernel(const float* __restrict__ uw,
                             const float* __restrict__ bias) {
    int o = blockIdx.x * blockDim.x + threadIdx.x;
    if (o >= OUT_DIM) return;
    float w[WIN];
#pragma unroll
    for (int j = 0; j < WIN; j++) w[j] = 0.015625f;   // 1/sqrt(4096)
#pragma unroll
    for (int t = 0; t < RSTEPS; t++) {
        const int d = t / 3, g = t % 3;
        float ang = uw[(size_t)d * IN_DIM * OUT_DIM + (size_t)o * OUT_DIM + g];
        float s, c;
        sincosf(ang, &s, &c);
        float nw[WIN];
        nw[0] = w[0]; nw[WIN - 1] = w[WIN - 1];
#pragma unroll
        for (int j = 1; j < WIN - 1; j++)
            nw[j] = c * w[j] - s * w[j + 1] + s * w[j - 1];
#pragma unroll
        for (int j = 0; j < WIN; j++) w[j] = nw[j];
    }
    g_pb[o] = w[CENTER] * w[CENTER] + bias[o];
}

// ---------------------------------------------------------------------------
// Kernel 2: split x -> (hi, lo) bf16
// ---------------------------------------------------------------------------
__global__ void split_x_kernel(const float* __restrict__ x) {
    size_t i = ((size_t)blockIdx.x * blockDim.x + threadIdx.x) * 4;
    float4 v = *(const float4*)(x + i);
    __nv_bfloat16 h0 = __float2bfloat16(v.x);
    __nv_bfloat16 h1 = __float2bfloat16(v.y);
    __nv_bfloat16 h2 = __float2bfloat16(v.z);
    __nv_bfloat16 h3 = __float2bfloat16(v.w);
    __nv_bfloat162* ph = (__nv_bfloat162*)(g_xhi + i);
    __nv_bfloat162* pl = (__nv_bfloat162*)(g_xlo + i);
    ph[0] = __nv_bfloat162(h0, h1);
    ph[1] = __nv_bfloat162(h2, h3);
    pl[0] = __nv_bfloat162(__float2bfloat16(v.x - __bfloat162float(h0)),
                           __float2bfloat16(v.y - __bfloat162float(h1)));
    pl[1] = __nv_bfloat162(__float2bfloat16(v.z - __bfloat162float(h2)),
                           __float2bfloat16(v.w - __bfloat162float(h3)));
}

// ---------------------------------------------------------------------------
// Kernel 3: transpose + split W[k][n] -> wT_hi/lo[n][k]
// ---------------------------------------------------------------------------
__global__ void split_w_kernel(const float* __restrict__ W) {
    __shared__ float t[32][33];
    const int n0 = blockIdx.x * 32, k0 = blockIdx.y * 32;
    const int tx = threadIdx.x, ty = threadIdx.y;   // 32 x 8
#pragma unroll
    for (int i = 0; i < 32; i += 8)
        t[ty + i][tx] = W[(size_t)(k0 + ty + i) * OUT_DIM + n0 + tx];
    __syncthreads();
#pragma unroll
    for (int i = 0; i < 32; i += 8) {
        float v = t[tx][ty + i];
        __nv_bfloat16 h = __float2bfloat16(v);
        size_t o = (size_t)(n0 + ty + i) * IN_DIM + k0 + tx;
        g_wThi[o] = h;
        g_wTlo[o] = __float2bfloat16(v - __bfloat162float(h));
    }
}

// ---------------------------------------------------------------------------
// Kernel 4: C = tanh(x @ W + g_pb) via bf16x3 mma.sync GEMM.
// 128x64x32 CTA tile, 8 warps (4x2), warp tile 32x32, 4-stage cp.async,
// 2 CTAs/SM so barrier epochs of one CTA overlap compute of the other.
// ---------------------------------------------------------------------------
__global__ __launch_bounds__(256, 2)
void gemm_bf16x3_kernel(float* __restrict__ out) {
    extern __shared__ char smem[];
    const uint32_t sb = smem_u32(smem);

    const int tid  = threadIdx.x;
    const int lane = tid & 31;
    const int wid  = tid >> 5;
    const int wm   = wid >> 1;          // 0..3  -> m offset wm*32
    const int wn   = wid & 1;           // 0..1  -> n offset wn*32
    const int gid  = lane >> 2;
    const int tg   = lane & 3;
    const int bm   = blockIdx.y * BM;
    const int bn   = blockIdx.x * BN;

    // --- global load mapping: 6 x 16B chunks per thread per stage ---
    const int rr = tid >> 2;            // rows 0..63
    const int cc = tid & 3;             // 16B chunk in 64B row

    const __nv_bfloat16* pAh0 = g_xhi  + (size_t)(bm + rr)      * IN_DIM + cc * 8;
    const __nv_bfloat16* pAh1 = g_xhi  + (size_t)(bm + rr + 64) * IN_DIM + cc * 8;
    const __nv_bfloat16* pAl0 = g_xlo  + (size_t)(bm + rr)      * IN_DIM + cc * 8;
    const __nv_bfloat16* pAl1 = g_xlo  + (size_t)(bm + rr + 64) * IN_DIM + cc * 8;
    const __nv_bfloat16* pBh  = g_wThi + (size_t)(bn + rr)      * IN_DIM + cc * 8;
    const __nv_bfloat16* pBl  = g_wTlo + (size_t)(bn + rr)      * IN_DIM + cc * 8;

    const uint32_t dAh0 = swz(AHI, rr,      cc);
    const uint32_t dAh1 = swz(AHI, rr + 64, cc);
    const uint32_t dAl0 = swz(ALO, rr,      cc);
    const uint32_t dAl1 = swz(ALO, rr + 64, cc);
    const uint32_t dBh  = swz(BHI, rr,      cc);
    const uint32_t dBl  = swz(BLO, rr,      cc);

    int kload = 0;
#define ISSUE_STAGE(stg)                                                     \
    do {                                                                     \
        uint32_t s_ = sb + (stg) * STAGE_BYTES;                              \
        cpasync16(s_ + dAh0, pAh0 + kload);                                  \
        cpasync16(s_ + dAh1, pAh1 + kload);                                  \
        cpasync16(s_ + dAl0, pAl0 + kload);                                  \
        cpasync16(s_ + dAl1, pAl1 + kload);                                  \
        cpasync16(s_ + dBh,  pBh  + kload);                                  \
        cpasync16(s_ + dBl,  pBl  + kload);                                  \
        kload += BK;                                                         \
    } while (0)

    // Prologue: stages 0..2
    ISSUE_STAGE(0); CP_COMMIT();
    ISSUE_STAGE(1); CP_COMMIT();
    ISSUE_STAGE(2); CP_COMMIT();

    float acc[2][4][4];
#pragma unroll
    for (int i = 0; i < 2; i++)
#pragma unroll
        for (int j = 0; j < 4; j++)
#pragma unroll
            for (int q = 0; q < 4; q++) acc[i][j][q] = 0.0f;

    // Per-lane ldmatrix logical coordinates
    const int a_rl = lane & 15;           // A: rows m0..m0+15
    const int a_ch = lane >> 4;           // A: +0 / +1 chunk
    const int b_rl = lane & 7;            // B: rows n0..n0+7
    const int b_ch = (lane >> 3) & 1;     // B: +0 / +1 chunk

    // Precomputed swizzled offsets (relative to stage base), both ks halves
    uint32_t oA[2][2], oB[2][4];
#pragma unroll
    for (int ks = 0; ks < 2; ks++) {
        const int ccA = ks * 2 + a_ch;
        const int ccB = ks * 2 + b_ch;
#pragma unroll
        for (int mi = 0; mi < 2; mi++)
            oA[ks][mi] = swz(0, wm * 32 + mi * 16 + a_rl, ccA);
#pragma unroll
        for (int ni = 0; ni < 4; ni++)
            oB[ks][ni] = swz(0, wn * 32 + ni * 8 + b_rl, ccB);
    }

    int stage = 0;
#pragma unroll 1
    for (int kt = 0; kt < NKT; kt++) {
        CP_WAIT2();
        __syncthreads();

        // Refill the stage freed at the previous iteration (kt+3)
        if (kt + 3 < NKT) {
            int nst = stage + 3; if (nst >= STAGES) nst -= STAGES;
            ISSUE_STAGE(nst);
        }
        CP_COMMIT();

        const uint32_t s_ = sb + stage * STAGE_BYTES;

#pragma unroll
        for (int ks = 0; ks < 2; ks++) {
            uint32_t ah[2][4], al[2][4], bh[4][2], bl[4][2];
#pragma unroll
            for (int mi = 0; mi < 2; mi++) {
                LDSM_X4(ah[mi], s_ + AHI + oA[ks][mi]);
                LDSM_X4(al[mi], s_ + ALO + oA[ks][mi]);
            }
#pragma unroll
            for (int ni = 0; ni < 4; ni++) {
                LDSM_X2(bh[ni], s_ + BHI + oB[ks][ni]);
                LDSM_X2(bl[ni], s_ + BLO + oB[ks][ni]);
            }
            // Product-major order: no back-to-back MMAs share an accumulator
#pragma unroll
            for (int mi = 0; mi < 2; mi++)
#pragma unroll
                for (int ni = 0; ni < 4; ni++)
                    MMA16816(acc[mi][ni], ah[mi], bh[ni]);
#pragma unroll
            for (int mi = 0; mi < 2; mi++)
#pragma unroll
                for (int ni = 0; ni < 4; ni++)
                    MMA16816(acc[mi][ni], ah[mi], bl[ni]);
#pragma unroll
            for (int mi = 0; mi < 2; mi++)
#pragma unroll
                for (int ni = 0; ni < 4; ni++)
                    MMA16816(acc[mi][ni], al[mi], bh[ni]);
        }
        stage++; if (stage >= STAGES) stage = 0;
    }

    // ------------------- epilogue: +pb, tanh, store -------------------
    float pbv[4][2];
#pragma unroll
    for (int ni = 0; ni < 4; ni++) {
        const int col = bn + wn * 32 + ni * 8 + tg * 2;
        pbv[ni][0] = g_pb[col];
        pbv[ni][1] = g_pb[col + 1];
    }
#pragma unroll
    for (int mi = 0; mi < 2; mi++) {
        const int r0 = bm + wm * 32 + mi * 16 + gid;
#pragma unroll
        for (int ni = 0; ni < 4; ni++) {
            const int col = bn + wn * 32 + ni * 8 + tg * 2;
            float2 v0, v1;
            v0.x = tanhf(acc[mi][ni][0] + pbv[ni][0]);
            v0.y = tanhf(acc[mi][ni][1] + pbv[ni][1]);
            v1.x = tanhf(acc[mi][ni][2] + pbv[ni][0]);
            v1.y = tanhf(acc[mi][ni][3] + pbv[ni][1]);
            *(float2*)(out + (size_t)r0 * OUT_DIM + col)       = v0;
            *(float2*)(out + (size_t)(r0 + 8) * OUT_DIM + col) = v1;
        }
    }
}

// ---------------------------------------------------------------------------
// Host launch
// ---------------------------------------------------------------------------
extern "C" void kernel_launch(void* const* d_in, const int* in_sizes, int n_in,
                              void* d_out, int out_size) {
    const float *x = nullptr, *uw = nullptr, *cw = nullptr, *cb = nullptr;
    for (int i = 0; i < n_in; i++) {
        switch (in_sizes[i]) {
            case BATCH * IN_DIM:           x  = (const float*)d_in[i]; break;
            case DEPTH * IN_DIM * OUT_DIM: uw = (const float*)d_in[i]; break;
            case IN_DIM * OUT_DIM:         cw = (const float*)d_in[i]; break;
            case OUT_DIM:                  cb = (const float*)d_in[i]; break;
            default: break;
        }
    }
    float* out = (float*)d_out;

    probs_kernel<<<OUT_DIM / 256, 256>>>(uw, cb);
    split_x_kernel<<<(BATCH * IN_DIM) / (4 * 256), 256>>>(x);
    split_w_kernel<<<dim3(OUT_DIM / 32, IN_DIM / 32), dim3(32, 8)>>>(cw);

    static int attr_done = 0;
    if (!attr_done) {
        cudaFuncSetAttribute(gemm_bf16x3_kernel,
                             cudaFuncAttributeMaxDynamicSharedMemorySize,
                             SMEM_TOTAL);
        attr_done = 1;
    }
    dim3 grid(OUT_DIM / BN, BATCH / BM);   // (32, 64)
    gemm_bf16x3_kernel<<<grid, 256, SMEM_TOTAL>>>(out);
}

// round 7
// speedup vs baseline: 1.1413x; 1.1046x over previous
#include <cuda_runtime.h>
#include <cuda_bf16.h>
#include <math.h>
#include <stdint.h>

// ---------------------------------------------------------------------------
// Problem constants
// ---------------------------------------------------------------------------
#define BATCH   8192
#define IN_DIM  4096
#define OUT_DIM 2048
#define DEPTH   9
#define RSTEPS  27
#define WIN     55
#define CENTER  27

// GEMM tiling: 128x64 CTA tile, 2 CTAs/SM
#define BM 128
#define BN 64
#define BK 32
#define NKT (IN_DIM / BK)            // 128
#define STAGES 4
// Stage layout: Ahi 8K | Alo 8K | Bhi 4K | Blo 4K
#define AHI 0
#define ALO 8192
#define BHI 16384
#define BLO 20480
#define STAGE_BYTES 24576
#define SMEM_TOTAL (STAGES * STAGE_BYTES)   // 98304/CTA -> 2 CTAs = 192KB/SM

// ---------------------------------------------------------------------------
// Device-global scratch (static: no runtime allocation)
// ---------------------------------------------------------------------------
__device__ float         g_pb[OUT_DIM];
__device__ __nv_bfloat16 g_xhi[(size_t)BATCH * IN_DIM];
__device__ __nv_bfloat16 g_xlo[(size_t)BATCH * IN_DIM];
__device__ __nv_bfloat16 g_wThi[(size_t)OUT_DIM * IN_DIM];   // W^T [N][K]
__device__ __nv_bfloat16 g_wTlo[(size_t)OUT_DIM * IN_DIM];

// ---------------------------------------------------------------------------
// PTX helpers (base sm_103 ISA only: cp.async / ldmatrix / mma.sync)
// ---------------------------------------------------------------------------
__device__ __forceinline__ uint32_t smem_u32(const void* p) {
    uint32_t a;
    asm("{ .reg .u64 t; cvta.to.shared.u64 t, %1; cvt.u32.u64 %0, t; }"
        : "=r"(a) : "l"(p));
    return a;
}
__device__ __forceinline__ void cpasync16(uint32_t dst, const void* src) {
    asm volatile("cp.async.cg.shared.global [%0], [%1], 16;"
                 :: "r"(dst), "l"(src));
}
#define CP_COMMIT() asm volatile("cp.async.commit_group;" ::: "memory")
#define CP_WAIT1()  asm volatile("cp.async.wait_group 1;"  ::: "memory")
#define CP_WAIT2()  asm volatile("cp.async.wait_group 2;"  ::: "memory")

#define LDSM_X4(d, a) \
    asm volatile("ldmatrix.sync.aligned.m8n8.x4.shared.b16 {%0,%1,%2,%3}, [%4];" \
        : "=r"((d)[0]), "=r"((d)[1]), "=r"((d)[2]), "=r"((d)[3]) : "r"(a))
#define LDSM_X2(d, a) \
    asm volatile("ldmatrix.sync.aligned.m8n8.x2.shared.b16 {%0,%1}, [%2];" \
        : "=r"((d)[0]), "=r"((d)[1]) : "r"(a))

#define MMA16816(c, a, b) \
    asm volatile("mma.sync.aligned.m16n8k16.row.col.f32.bf16.bf16.f32 " \
        "{%0,%1,%2,%3}, {%4,%5,%6,%7}, {%8,%9}, {%0,%1,%2,%3};" \
        : "+f"((c)[0]), "+f"((c)[1]), "+f"((c)[2]), "+f"((c)[3]) \
        : "r"((a)[0]), "r"((a)[1]), "r"((a)[2]), "r"((a)[3]), \
          "r"((b)[0]), "r"((b)[1]))

// Swizzled smem offset for logical (row, 16B-chunk cc 0..3) of a 64B-row tile.
__device__ __forceinline__ uint32_t swz(uint32_t base, int row, int cc) {
    int p  = row >> 1;
    int c8 = ((row & 1) << 2) | cc;
    return base + p * 128 + ((c8 ^ (p & 7)) << 4);
}

// ---------------------------------------------------------------------------
// Kernel 1: universal probs (dependency-cone trick) + bias -> g_pb
// ---------------------------------------------------------------------------
__global__ void probs_kernel(const float* __restrict__ uw,
                             const float* __restrict__ bias) {
    int o = blockIdx.x * blockDim.x + threadIdx.x;
    if (o >= OUT_DIM) return;
    float w[WIN];
#pragma unroll
    for (int j = 0; j < WIN; j++) w[j] = 0.015625f;   // 1/sqrt(4096)
#pragma unroll
    for (int t = 0; t < RSTEPS; t++) {
        const int d = t / 3, g = t % 3;
        float ang = uw[(size_t)d * IN_DIM * OUT_DIM + (size_t)o * OUT_DIM + g];
        float s, c;
        sincosf(ang, &s, &c);
        float nw[WIN];
        nw[0] = w[0]; nw[WIN - 1] = w[WIN - 1];
#pragma unroll
        for (int j = 1; j < WIN - 1; j++)
            nw[j] = c * w[j] - s * w[j + 1] + s * w[j - 1];
#pragma unroll
        for (int j = 0; j < WIN; j++) w[j] = nw[j];
    }
    g_pb[o] = w[CENTER] * w[CENTER] + bias[o];
}

// ---------------------------------------------------------------------------
// Kernel 2: split x -> (hi, lo) bf16
// ---------------------------------------------------------------------------
__global__ void split_x_kernel(const float* __restrict__ x) {
    size_t i = ((size_t)blockIdx.x * blockDim.x + threadIdx.x) * 4;
    float4 v = *(const float4*)(x + i);
    __nv_bfloat16 h0 = __float2bfloat16(v.x);
    __nv_bfloat16 h1 = __float2bfloat16(v.y);
    __nv_bfloat16 h2 = __float2bfloat16(v.z);
    __nv_bfloat16 h3 = __float2bfloat16(v.w);
    __nv_bfloat162* ph = (__nv_bfloat162*)(g_xhi + i);
    __nv_bfloat162* pl = (__nv_bfloat162*)(g_xlo + i);
    ph[0] = __nv_bfloat162(h0, h1);
    ph[1] = __nv_bfloat162(h2, h3);
    pl[0] = __nv_bfloat162(__float2bfloat16(v.x - __bfloat162float(h0)),
                           __float2bfloat16(v.y - __bfloat162float(h1)));
    pl[1] = __nv_bfloat162(__float2bfloat16(v.z - __bfloat162float(h2)),
                           __float2bfloat16(v.w - __bfloat162float(h3)));
}

// ---------------------------------------------------------------------------
// Kernel 3: transpose + split W[k][n] -> wT_hi/lo[n][k]
// ---------------------------------------------------------------------------
__global__ void split_w_kernel(const float* __restrict__ W) {
    __shared__ float t[32][33];
    const int n0 = blockIdx.x * 32, k0 = blockIdx.y * 32;
    const int tx = threadIdx.x, ty = threadIdx.y;   // 32 x 8
#pragma unroll
    for (int i = 0; i < 32; i += 8)
        t[ty + i][tx] = W[(size_t)(k0 + ty + i) * OUT_DIM + n0 + tx];
    __syncthreads();
#pragma unroll
    for (int i = 0; i < 32; i += 8) {
        float v = t[tx][ty + i];
        __nv_bfloat16 h = __float2bfloat16(v);
        size_t o = (size_t)(n0 + ty + i) * IN_DIM + k0 + tx;
        g_wThi[o] = h;
        g_wTlo[o] = __float2bfloat16(v - __bfloat162float(h));
    }
}

// ---------------------------------------------------------------------------
// Kernel 4: C = tanh(x @ W + g_pb) via bf16x3 mma.sync GEMM.
// 128x64x32 CTA tile, 8 warps (4x2), warp tile 32x32, 4-stage cp.async,
// 2 CTAs/SM, register-level fragment double buffering: hi-fragments for
// ks-phase p are LDSM'd during phase p-1's MMA stream, so tensor issue is
// never blocked on ldmatrix latency.
// ---------------------------------------------------------------------------
__global__ __launch_bounds__(256, 2)
void gemm_bf16x3_kernel(float* __restrict__ out) {
    extern __shared__ char smem[];
    const uint32_t sb = smem_u32(smem);

    const int tid  = threadIdx.x;
    const int lane = tid & 31;
    const int wid  = tid >> 5;
    const int wm   = wid >> 1;          // 0..3  -> m offset wm*32
    const int wn   = wid & 1;           // 0..1  -> n offset wn*32
    const int gid  = lane >> 2;
    const int tg   = lane & 3;
    const int bm   = blockIdx.y * BM;
    const int bn   = blockIdx.x * BN;

    // --- global load mapping: 6 x 16B chunks per thread per stage ---
    const int rr = tid >> 2;            // rows 0..63
    const int cc = tid & 3;             // 16B chunk in 64B row

    const __nv_bfloat16* pAh0 = g_xhi  + (size_t)(bm + rr)      * IN_DIM + cc * 8;
    const __nv_bfloat16* pAh1 = g_xhi  + (size_t)(bm + rr + 64) * IN_DIM + cc * 8;
    const __nv_bfloat16* pAl0 = g_xlo  + (size_t)(bm + rr)      * IN_DIM + cc * 8;
    const __nv_bfloat16* pAl1 = g_xlo  + (size_t)(bm + rr + 64) * IN_DIM + cc * 8;
    const __nv_bfloat16* pBh  = g_wThi + (size_t)(bn + rr)      * IN_DIM + cc * 8;
    const __nv_bfloat16* pBl  = g_wTlo + (size_t)(bn + rr)      * IN_DIM + cc * 8;

    const uint32_t dAh0 = swz(AHI, rr,      cc);
    const uint32_t dAh1 = swz(AHI, rr + 64, cc);
    const uint32_t dAl0 = swz(ALO, rr,      cc);
    const uint32_t dAl1 = swz(ALO, rr + 64, cc);
    const uint32_t dBh  = swz(BHI, rr,      cc);
    const uint32_t dBl  = swz(BLO, rr,      cc);

    int kload = 0;
#define ISSUE_STAGE(stg)                                                     \
    do {                                                                     \
        uint32_t s_ = sb + (stg) * STAGE_BYTES;                              \
        cpasync16(s_ + dAh0, pAh0 + kload);                                  \
        cpasync16(s_ + dAh1, pAh1 + kload);                                  \
        cpasync16(s_ + dAl0, pAl0 + kload);                                  \
        cpasync16(s_ + dAl1, pAl1 + kload);                                  \
        cpasync16(s_ + dBh,  pBh  + kload);                                  \
        cpasync16(s_ + dBl,  pBl  + kload);                                  \
        kload += BK;                                                         \
    } while (0)

    // Prologue: fill stages 0..2 (stage 3 filled by iteration kt=0)
    ISSUE_STAGE(0); CP_COMMIT();
    ISSUE_STAGE(1); CP_COMMIT();
    ISSUE_STAGE(2); CP_COMMIT();

    float acc[2][4][4];
#pragma unroll
    for (int i = 0; i < 2; i++)
#pragma unroll
        for (int j = 0; j < 4; j++)
#pragma unroll
            for (int q = 0; q < 4; q++) acc[i][j][q] = 0.0f;

    // Per-lane ldmatrix logical coordinates
    const int a_rl = lane & 15;           // A: rows m0..m0+15
    const int a_ch = lane >> 4;           // A: +0 / +1 chunk
    const int b_rl = lane & 7;            // B: rows n0..n0+7
    const int b_ch = (lane >> 3) & 1;     // B: +0 / +1 chunk

    // Precomputed swizzled offsets (relative to stage base), both ks halves
    uint32_t oA[2][2], oB[2][4];
#pragma unroll
    for (int ks = 0; ks < 2; ks++) {
        const int ccA = ks * 2 + a_ch;
        const int ccB = ks * 2 + b_ch;
#pragma unroll
        for (int mi = 0; mi < 2; mi++)
            oA[ks][mi] = swz(0, wm * 32 + mi * 16 + a_rl, ccA);
#pragma unroll
        for (int ni = 0; ni < 4; ni++)
            oB[ks][ni] = swz(0, wn * 32 + ni * 8 + b_rl, ccB);
    }

    // Fragment registers: hi double-buffered (phase 0 / phase 1), lo single
    uint32_t ah0[2][4], ah1[2][4];        // A-hi, phase buffers
    uint32_t bh0[4][2], bh1[4][2];        // B-hi, phase buffers
    uint32_t al[2][4],  bl[4][2];         // lo, just-in-time

#define LOAD_HI(AH, BH, SBASE, KS)                                           \
    do {                                                                     \
        LDSM_X4(AH[0], (SBASE) + AHI + oA[KS][0]);                           \
        LDSM_X4(AH[1], (SBASE) + AHI + oA[KS][1]);                           \
        LDSM_X2(BH[0], (SBASE) + BHI + oB[KS][0]);                           \
        LDSM_X2(BH[1], (SBASE) + BHI + oB[KS][1]);                           \
        LDSM_X2(BH[2], (SBASE) + BHI + oB[KS][2]);                           \
        LDSM_X2(BH[3], (SBASE) + BHI + oB[KS][3]);                           \
    } while (0)

#define LOAD_LO(SBASE, KS)                                                   \
    do {                                                                     \
        LDSM_X4(al[0], (SBASE) + ALO + oA[KS][0]);                           \
        LDSM_X4(al[1], (SBASE) + ALO + oA[KS][1]);                           \
        LDSM_X2(bl[0], (SBASE) + BLO + oB[KS][0]);                           \
        LDSM_X2(bl[1], (SBASE) + BLO + oB[KS][1]);                           \
        LDSM_X2(bl[2], (SBASE) + BLO + oB[KS][2]);                           \
        LDSM_X2(bl[3], (SBASE) + BLO + oB[KS][3]);                           \
    } while (0)

    // hh first (deps satisfied long ago), then hl (bl loaded this phase,
    // covered by the 8 hh MMAs), then lh.
#define MMA_PHASE(AH, BH)                                                    \
    do {                                                                     \
        _Pragma("unroll")                                                    \
        for (int mi = 0; mi < 2; mi++)                                       \
            _Pragma("unroll")                                                \
            for (int ni = 0; ni < 4; ni++)                                   \
                MMA16816(acc[mi][ni], AH[mi], BH[ni]);                       \
        _Pragma("unroll")                                                    \
        for (int mi = 0; mi < 2; mi++)                                       \
            _Pragma("unroll")                                                \
            for (int ni = 0; ni < 4; ni++)                                   \
                MMA16816(acc[mi][ni], AH[mi], bl[ni]);                       \
        _Pragma("unroll")                                                    \
        for (int mi = 0; mi < 2; mi++)                                       \
            _Pragma("unroll")                                                \
            for (int ni = 0; ni < 4; ni++)                                   \
                MMA16816(acc[mi][ni], al[mi], BH[ni]);                       \
    } while (0)

    // Prologue fragment load: phase-0 hi of chunk 0 (stage 0 ready after
    // wait+barrier; wait_group 2 with 3 commits outstanding -> g0 done)
    CP_WAIT2();
    __syncthreads();
    LOAD_HI(ah0, bh0, sb + 0 * STAGE_BYTES, 0);

#pragma unroll 1
    for (int kt = 0; kt < NKT; kt++) {
        // wait_group 1: groups up to kt+1 complete -> stage kt+1 readable
        CP_WAIT1();
        __syncthreads();
        // refill slot (kt+3)%4 = (kt-1)%4, fully consumed at iter kt-1
        if (kt + 3 < NKT) {
            ISSUE_STAGE((kt + 3) & 3);
        }
        CP_COMMIT();

        const uint32_t s_cur = sb + (kt & 3) * STAGE_BYTES;
        const uint32_t s_nxt = sb + ((kt + 1) & 3) * STAGE_BYTES;

        // ---- phase ks=0: consume (ah0,bh0), prefetch ks=1 hi ----
        LOAD_LO(s_cur, 0);
        LOAD_HI(ah1, bh1, s_cur, 1);
        MMA_PHASE(ah0, bh0);

        // ---- phase ks=1: consume (ah1,bh1), prefetch next chunk ks=0 hi ----
        LOAD_LO(s_cur, 1);
        LOAD_HI(ah0, bh0, s_nxt, 0);    // stale read at kt=NKT-1: never consumed
        MMA_PHASE(ah1, bh1);
    }

    // ------------------- epilogue: +pb, tanh, store -------------------
    float pbv[4][2];
#pragma unroll
    for (int ni = 0; ni < 4; ni++) {
        const int col = bn + wn * 32 + ni * 8 + tg * 2;
        pbv[ni][0] = g_pb[col];
        pbv[ni][1] = g_pb[col + 1];
    }
#pragma unroll
    for (int mi = 0; mi < 2; mi++) {
        const int r0 = bm + wm * 32 + mi * 16 + gid;
#pragma unroll
        for (int ni = 0; ni < 4; ni++) {
            const int col = bn + wn * 32 + ni * 8 + tg * 2;
            float2 v0, v1;
            v0.x = tanhf(acc[mi][ni][0] + pbv[ni][0]);
            v0.y = tanhf(acc[mi][ni][1] + pbv[ni][1]);
            v1.x = tanhf(acc[mi][ni][2] + pbv[ni][0]);
            v1.y = tanhf(acc[mi][ni][3] + pbv[ni][1]);
            *(float2*)(out + (size_t)r0 * OUT_DIM + col)       = v0;
            *(float2*)(out + (size_t)(r0 + 8) * OUT_DIM + col) = v1;
        }
    }
}

// ---------------------------------------------------------------------------
// Host launch
// ---------------------------------------------------------------------------
extern "C" void kernel_launch(void* const* d_in, const int* in_sizes, int n_in,
                              void* d_out, int out_size) {
    const float *x = nullptr, *uw = nullptr, *cw = nullptr, *cb = nullptr;
    for (int i = 0; i < n_in; i++) {
        switch (in_sizes[i]) {
            case BATCH * IN_DIM:           x  = (const float*)d_in[i]; break;
            case DEPTH * IN_DIM * OUT_DIM: uw = (const float*)d_in[i]; break;
            case IN_DIM * OUT_DIM:         cw = (const float*)d_in[i]; break;
            case OUT_DIM:                  cb = (const float*)d_in[i]; break;
            default: break;
        }
    }
    float* out = (float*)d_out;

    probs_kernel<<<OUT_DIM / 256, 256>>>(uw, cb);
    split_x_kernel<<<(BATCH * IN_DIM) / (4 * 256), 256>>>(x);
    split_w_kernel<<<dim3(OUT_DIM / 32, IN_DIM / 32), dim3(32, 8)>>>(cw);

    static int attr_done = 0;
    if (!attr_done) {
        cudaFuncSetAttribute(gemm_bf16x3_kernel,
                             cudaFuncAttributeMaxDynamicSharedMemorySize,
                             SMEM_TOTAL);
        attr_done = 1;
    }
    dim3 grid(OUT_DIM / BN, BATCH / BM);   // (32, 64)
    gemm_bf16x3_kernel<<<grid, 256, SMEM_TOTAL>>>(out);
}